// round 14
// baseline (speedup 1.0000x reference)
#include <cuda_runtime.h>
#include <cstdint>

// Problem constants (fixed by the dataset: x [32,256,512], embeddings [8192,512])
#define N_TOK   8192
#define K_CODES 8192
#define DIM     512

// Argmin-GEMM tiling: persistent blocks (2 CTAs/SM), items = (mtile, split)
#define TM 128       // token rows per item
#define TN 128       // codes per k-chunk
#define TD 32        // D-slice per smem stage
#define SPLITS 32    // K splits (item granularity for load balance)
#define KS (K_CODES / SPLITS)        // 256
#define NCHUNK (KS / TN)             // 2
#define NSTAGE (DIM / TD)            // 16
#define MTILES (N_TOK / TM)          // 64
#define ITEMS (MTILES * SPLITS)      // 2048
#define GRID_PERSIST 296             // 2 CTAs per SM x 148 SMs

#define TILE_STRIDE (TM + 2)         // 130 floats (even -> LDS.64 aligned)
#define TILE_FLOATS (TD * TILE_STRIDE)              // 4160
#define SMEM_FLOATS (3 * TILE_FLOATS)               // xs + ef + er = 12480
#define SMEM_BYTES  (SMEM_FLOATS * 4)               // 49920 (> 48KB -> dynamic smem)

// ---------------- device scratch (no allocations allowed) ----------------
// Referenced ONLY from device code (host-side use of a __device__ symbol is the
// host shadow address -> UVM pool allocation -> harness mem-guard failure).
__device__ float g_esq[K_CODES];
__device__ float g_xsq[N_TOK];
__device__ float g_pval[SPLITS][N_TOK];
__device__ int   g_pidx[SPLITS][N_TOK];
__device__ float g_rowsq[N_TOK];

// ---------------- packed f32x2 helpers (sm_100a Blackwell) ----------------
// Each 32-bit lane of fma.rn.f32x2 is an independent IEEE fp32 FMA, so a packed
// accumulator chain over ascending d is bit-identical to a scalar FFMA chain.
__device__ __forceinline__ unsigned long long pack2(float a, float b) {
    unsigned long long r;
    asm("mov.b64 %0, {%1, %2};" : "=l"(r) : "f"(a), "f"(b));
    return r;
}
__device__ __forceinline__ void unpack2(unsigned long long v, float& a, float& b) {
    asm("mov.b64 {%0, %1}, %2;" : "=f"(a), "=f"(b) : "l"(v));
}
__device__ __forceinline__ unsigned long long fma2(unsigned long long a,
                                                   unsigned long long b,
                                                   unsigned long long c) {
    unsigned long long d;
    asm("fma.rn.f32x2 %0, %1, %2, %3;" : "=l"(d) : "l"(a), "l"(b), "l"(c));
    return d;
}

// ---------------- kernel 1a: e_sq[k] = sum_d E[k][d]^2 ----------------
// XLA row-reduce replica: lane-strided ascending accumulation, NON-FUSED
// mul+add, butterfly tree. (Verified bit-exact R9-R13.)
__global__ void vq_esq(const float* __restrict__ E) {
    int w = (blockIdx.x * blockDim.x + threadIdx.x) >> 5;
    int lane = threadIdx.x & 31;
    if (w >= K_CODES) return;
    const float* row = E + (size_t)w * DIM;
    float s = 0.f;
    #pragma unroll
    for (int d = lane; d < DIM; d += 32) {
        float v = __ldg(row + d);
        s = __fadd_rn(s, __fmul_rn(v, v));
    }
    #pragma unroll
    for (int o = 16; o > 0; o >>= 1) s = __fadd_rn(s, __shfl_xor_sync(0xffffffffu, s, o));
    if (lane == 0) g_esq[w] = s;
}

// ---------------- kernel 1b: x_sq[n] = sum_d x[n][d]^2 ----------------
__global__ void vq_xsq(const float* __restrict__ x) {
    int w = (blockIdx.x * blockDim.x + threadIdx.x) >> 5;
    int lane = threadIdx.x & 31;
    if (w >= N_TOK) return;
    const float* row = x + (size_t)w * DIM;
    float s = 0.f;
    #pragma unroll
    for (int d = lane; d < DIM; d += 32) {
        float v = __ldg(row + d);
        s = __fadd_rn(s, __fmul_rn(v, v));
    }
    #pragma unroll
    for (int o = 16; o > 0; o >>= 1) s = __fadd_rn(s, __shfl_xor_sync(0xffffffffu, s, o));
    if (lane == 0) g_xsq[w] = s;
}

// ---------------- kernel 2: persistent fused fp32-dot + argmin ----------------
// R11 skeleton (proven fastest scheduling) with the 8 swap-MOVs/d replaced by a
// pre-swapped e tile in smem:
//   ef[d][c]   = e_c  (forward pairs)     er[d][c^1] = e_c  (swapped pairs)
// Per d: 4 xp + 4 ef + 4 er LDS.64 (hoisted) + 32 FFMA2, zero MOVs.
//   accD[q][p] lanes = (r0*c0, r1*c1), accA[q][p] lanes = (r0*c1, r1*c0)
// Every lane is a serial ascending-d fp32 FMA chain -> bit-identical to R11.
// dist[n][k] = fl( fl(x_sq[n] - 2*dot) + e_sq[k] ), first-index tie-break.
__global__ __launch_bounds__(256, 2) void vq_argmin(const float* __restrict__ x,
                                                    const float* __restrict__ E) {
    extern __shared__ __align__(16) float smem[];
    float (*xs)[TILE_STRIDE] = reinterpret_cast<float(*)[TILE_STRIDE]>(smem);
    float (*ef)[TILE_STRIDE] = reinterpret_cast<float(*)[TILE_STRIDE]>(smem + TILE_FLOATS);
    float (*er)[TILE_STRIDE] = reinterpret_cast<float(*)[TILE_STRIDE]>(smem + 2 * TILE_FLOATS);

    const int t  = threadIdx.x;
    const int tx = t & 15;
    const int ty = t >> 4;
    const int lrow  = t >> 1;          // loader row 0..127
    const int lrowx = lrow ^ 1;        // pair-partner slot for the swapped e copy
    const int lhalf = (t & 1) * 16;    // loader d-offset (16 floats each)

    for (int item = blockIdx.x; item < ITEMS; item += GRID_PERSIST) {
        const int mtile = item >> 5;               // / SPLITS
        const int split = item & (SPLITS - 1);
        const int m0 = mtile * TM;
        const int kbase = split * KS;

        float xsqv[8];
        #pragma unroll
        for (int q = 0; q < 4; q++) {
            xsqv[2 * q]     = g_xsq[m0 + 32 * q + 2 * ty];
            xsqv[2 * q + 1] = g_xsq[m0 + 32 * q + 2 * ty + 1];
        }

        float bestv[8];
        int   besti[8];
        #pragma unroll
        for (int i = 0; i < 8; i++) { bestv[i] = 3.4e38f; besti[i] = 0; }

        const unsigned long long zero2 = pack2(0.f, 0.f);

        for (int c = 0; c < NCHUNK; c++) {
            const int k0 = kbase + c * TN;

            unsigned long long accD[4][4], accA[4][4];
            #pragma unroll
            for (int q = 0; q < 4; q++)
                #pragma unroll
                for (int p = 0; p < 4; p++) { accD[q][p] = zero2; accA[q][p] = zero2; }

            for (int s = 0; s < NSTAGE; s++) {
                const int d0 = s * TD;
                __syncthreads();   // previous stage's readers done
                {   // x: row lrow, 16 d-values, transposed store
                    const float* xp = &x[(size_t)(m0 + lrow) * DIM + d0 + lhalf];
                    #pragma unroll
                    for (int v4 = 0; v4 < 4; v4++) {
                        float4 a = *reinterpret_cast<const float4*>(xp + 4 * v4);
                        xs[lhalf + 4 * v4 + 0][lrow] = a.x;
                        xs[lhalf + 4 * v4 + 1][lrow] = a.y;
                        xs[lhalf + 4 * v4 + 2][lrow] = a.z;
                        xs[lhalf + 4 * v4 + 3][lrow] = a.w;
                    }
                    // e: row lrow, stored forward (ef[d][c]) and swapped (er[d][c^1])
                    const float* epg = &E[(size_t)(k0 + lrow) * DIM + d0 + lhalf];
                    #pragma unroll
                    for (int v4 = 0; v4 < 4; v4++) {
                        float4 b = *reinterpret_cast<const float4*>(epg + 4 * v4);
                        ef[lhalf + 4 * v4 + 0][lrow] = b.x;
                        ef[lhalf + 4 * v4 + 1][lrow] = b.y;
                        ef[lhalf + 4 * v4 + 2][lrow] = b.z;
                        ef[lhalf + 4 * v4 + 3][lrow] = b.w;
                        er[lhalf + 4 * v4 + 0][lrowx] = b.x;
                        er[lhalf + 4 * v4 + 1][lrowx] = b.y;
                        er[lhalf + 4 * v4 + 2][lrowx] = b.z;
                        er[lhalf + 4 * v4 + 3][lrowx] = b.w;
                    }
                }
                __syncthreads();
                #pragma unroll 8
                for (int d = 0; d < TD; d++) {
                    unsigned long long xp[4];
                    #pragma unroll
                    for (int q = 0; q < 4; q++)
                        xp[q] = *reinterpret_cast<const unsigned long long*>(&xs[d][32 * q + 2 * ty]);
                    #pragma unroll
                    for (int p = 0; p < 4; p++) {
                        unsigned long long efp =
                            *reinterpret_cast<const unsigned long long*>(&ef[d][32 * p + 2 * tx]);
                        unsigned long long erp =
                            *reinterpret_cast<const unsigned long long*>(&er[d][32 * p + 2 * tx]);
                        #pragma unroll
                        for (int q = 0; q < 4; q++) {
                            accD[q][p] = fma2(xp[q], efp, accD[q][p]);
                            accA[q][p] = fma2(xp[q], erp, accA[q][p]);
                        }
                    }
                }
            }

            // epilogue: dist = fl( fl(x_sq - 2*dot) + e_sq ); ascending k, strict <
            #pragma unroll
            for (int p = 0; p < 4; p++) {
                int c0 = k0 + 32 * p + 2 * tx;
                float eq0 = __ldg(&g_esq[c0]);
                float eq1 = __ldg(&g_esq[c0 + 1]);
                #pragma unroll
                for (int q = 0; q < 4; q++) {
                    float d00, d11, a01, a10;
                    unpack2(accD[q][p], d00, d11);   // (r0*c0, r1*c1)
                    unpack2(accA[q][p], a01, a10);   // (r0*c1, r1*c0)
                    float s0 = __fadd_rn(fmaf(-2.f, d00, xsqv[2 * q]), eq0);
                    if (s0 < bestv[2 * q]) { bestv[2 * q] = s0; besti[2 * q] = c0; }
                    float s1 = __fadd_rn(fmaf(-2.f, a01, xsqv[2 * q]), eq1);
                    if (s1 < bestv[2 * q]) { bestv[2 * q] = s1; besti[2 * q] = c0 + 1; }
                    float s2 = __fadd_rn(fmaf(-2.f, a10, xsqv[2 * q + 1]), eq0);
                    if (s2 < bestv[2 * q + 1]) { bestv[2 * q + 1] = s2; besti[2 * q + 1] = c0; }
                    float s3 = __fadd_rn(fmaf(-2.f, d11, xsqv[2 * q + 1]), eq1);
                    if (s3 < bestv[2 * q + 1]) { bestv[2 * q + 1] = s3; besti[2 * q + 1] = c0 + 1; }
                }
            }
        }

        // cross-thread reduction per item; alias dead tile buffers
        __syncthreads();
        float* rv = smem;                                   // [TM][16] = 8 KB
        int*   ri = reinterpret_cast<int*>(smem + TM * 16); // [TM][16] = 8 KB
        #pragma unroll
        for (int q = 0; q < 4; q++)
            #pragma unroll
            for (int s2 = 0; s2 < 2; s2++) {
                int row = 32 * q + 2 * ty + s2;
                rv[row * 16 + tx] = bestv[2 * q + s2];
                ri[row * 16 + tx] = besti[2 * q + s2];
            }
        __syncthreads();
        if (t < TM) {
            float bv = rv[t * 16];
            int   bi = ri[t * 16];
            #pragma unroll
            for (int j = 1; j < 16; j++) {
                float v = rv[t * 16 + j];
                int idx = ri[t * 16 + j];
                if (v < bv || (v == bv && idx < bi)) { bv = v; bi = idx; }
            }
            g_pval[split][m0 + t] = bv;
            g_pidx[split][m0 + t] = bi;
        }
        // next item's first __syncthreads() orders these reads vs buffer reuse
    }
}

// ---------------- kernel 3: combine splits, gather, write q_st + indices ----------------
__global__ void vq_combine(const float* __restrict__ x, const float* __restrict__ E,
                           float* __restrict__ out) {
    int gw   = (blockIdx.x * blockDim.x + threadIdx.x) >> 5;  // one warp per token row
    int lane = threadIdx.x & 31;
    if (gw >= N_TOK) return;

    float bv = g_pval[0][gw];
    int   bi = g_pidx[0][gw];
    #pragma unroll
    for (int s = 1; s < SPLITS; s++) {
        float v = g_pval[s][gw];
        int idx = g_pidx[s][gw];
        if (v < bv || (v == bv && idx < bi)) { bv = v; bi = idx; }
    }

    const float* er = E + (size_t)bi * DIM;
    const float* xr = x + (size_t)gw * DIM;
    float* qr = out + (size_t)gw * DIM;
    float sq = 0.f;
    #pragma unroll
    for (int d = lane; d < DIM; d += 32) {
        float e  = er[d];
        float xv = xr[d];
        qr[d] = __fadd_rn(xv, __fadd_rn(e, -xv));  // straight-through: fl(x + fl(q - x))
        float df = __fadd_rn(xv, -e);
        sq = __fadd_rn(sq, __fmul_rn(df, df));
    }
    #pragma unroll
    for (int o = 16; o > 0; o >>= 1) sq = __fadd_rn(sq, __shfl_xor_sync(0xffffffffu, sq, o));
    if (lane == 0) {
        g_rowsq[gw] = sq;
        out[(size_t)N_TOK * DIM + gw] = (float)bi;   // indices as float32
    }
}

// ---------------- kernel 4: deterministic loss reduction ----------------
__global__ void vq_loss(float* __restrict__ out) {
    __shared__ float red[256];
    int t = threadIdx.x;
    float s = 0.f;
    for (int i = t; i < N_TOK; i += 256) s += g_rowsq[i];
    red[t] = s;
    __syncthreads();
    #pragma unroll
    for (int o = 128; o > 0; o >>= 1) {
        if (t < o) red[t] += red[t + o];
        __syncthreads();
    }
    if (t == 0) {
        float mse = red[0] / (float)((size_t)N_TOK * DIM);
        size_t base = (size_t)N_TOK * DIM + N_TOK;
        out[base + 0] = 0.25f * mse;   // commitment_loss
        out[base + 1] = mse;           // codebook_loss
        out[base + 2] = 1.25f * mse;   // total_loss
    }
}

// ---------------- entry point ----------------
extern "C" void kernel_launch(void* const* d_in, const int* in_sizes, int n_in,
                              void* d_out, int out_size) {
    (void)in_sizes; (void)n_in; (void)out_size;
    const float* x = (const float*)d_in[0];   // [32*256, 512]
    const float* E = (const float*)d_in[1];   // [8192, 512]
    float* out = (float*)d_out;

    // Opt into >48KB dynamic smem (attribute set, not an allocation; idempotent,
    // executes immediately — not a captured stream op).
    cudaFuncSetAttribute(vq_argmin, cudaFuncAttributeMaxDynamicSharedMemorySize, SMEM_BYTES);

    vq_esq<<<K_CODES * 32 / 256, 256>>>(E);
    vq_xsq<<<N_TOK * 32 / 256, 256>>>(x);
    vq_argmin<<<GRID_PERSIST, 256, SMEM_BYTES>>>(x, E);
    vq_combine<<<N_TOK * 32 / 256, 256>>>(x, E, out);
    vq_loss<<<1, 256>>>(out);
}

// round 15
// speedup vs baseline: 1.1254x; 1.1254x over previous
#include <cuda_runtime.h>
#include <cstdint>

// Problem constants (fixed by the dataset: x [32,256,512], embeddings [8192,512])
#define N_TOK   8192
#define K_CODES 8192
#define DIM     512

// Argmin-GEMM tiling: persistent blocks (2 CTAs/SM), items = (mtile, split)
#define TM 128       // token rows per item
#define TN 128       // codes per k-chunk
#define TD 32        // D-slice per smem stage
#define SPLITS 32    // K splits (item granularity for load balance)
#define KS (K_CODES / SPLITS)        // 256
#define NCHUNK (KS / TN)             // 2
#define NSTAGE (DIM / TD)            // 16
#define MTILES (N_TOK / TM)          // 64
#define ITEMS (MTILES * SPLITS)      // 2048
#define GRID_PERSIST 296             // 2 CTAs per SM x 148 SMs

#define TILE_STRIDE (TM + 2)                     // 130 floats (even -> LDS.64 aligned)
#define TILE_FLOATS (TD * TILE_STRIDE)           // 4160
#define BUF_FLOATS  (2 * TILE_FLOATS)            // xs + es per buffer = 8320
#define SMEM_FLOATS (2 * BUF_FLOATS)             // double buffered = 16640
#define SMEM_BYTES  (SMEM_FLOATS * 4)            // 66560 (> 48KB -> dynamic smem)

// ---------------- device scratch (no allocations allowed) ----------------
// Referenced ONLY from device code (host-side use of a __device__ symbol is the
// host shadow address -> UVM pool allocation -> harness mem-guard failure).
__device__ float g_esq[K_CODES];
__device__ float g_xsq[N_TOK];
__device__ float g_pval[SPLITS][N_TOK];
__device__ int   g_pidx[SPLITS][N_TOK];
__device__ float g_rowsq[N_TOK];

// ---------------- packed f32x2 helpers (sm_100a Blackwell) ----------------
// Each 32-bit lane of fma.rn.f32x2 is an independent IEEE fp32 FMA, so a packed
// accumulator chain over ascending d is bit-identical to a scalar FFMA chain.
__device__ __forceinline__ unsigned long long pack2(float a, float b) {
    unsigned long long r;
    asm("mov.b64 %0, {%1, %2};" : "=l"(r) : "f"(a), "f"(b));
    return r;
}
__device__ __forceinline__ void unpack2(unsigned long long v, float& a, float& b) {
    asm("mov.b64 {%0, %1}, %2;" : "=f"(a), "=f"(b) : "l"(v));
}
__device__ __forceinline__ unsigned long long fma2(unsigned long long a,
                                                   unsigned long long b,
                                                   unsigned long long c) {
    unsigned long long d;
    asm("fma.rn.f32x2 %0, %1, %2, %3;" : "=l"(d) : "l"(a), "l"(b), "l"(c));
    return d;
}

// ---------------- kernel 1a: e_sq[k] = sum_d E[k][d]^2 ----------------
// XLA row-reduce replica: lane-strided ascending accumulation, NON-FUSED
// mul+add, butterfly tree. (Verified bit-exact R9-R14.)
__global__ void vq_esq(const float* __restrict__ E) {
    int w = (blockIdx.x * blockDim.x + threadIdx.x) >> 5;
    int lane = threadIdx.x & 31;
    if (w >= K_CODES) return;
    const float* row = E + (size_t)w * DIM;
    float s = 0.f;
    #pragma unroll
    for (int d = lane; d < DIM; d += 32) {
        float v = __ldg(row + d);
        s = __fadd_rn(s, __fmul_rn(v, v));
    }
    #pragma unroll
    for (int o = 16; o > 0; o >>= 1) s = __fadd_rn(s, __shfl_xor_sync(0xffffffffu, s, o));
    if (lane == 0) g_esq[w] = s;
}

// ---------------- kernel 1b: x_sq[n] = sum_d x[n][d]^2 ----------------
__global__ void vq_xsq(const float* __restrict__ x) {
    int w = (blockIdx.x * blockDim.x + threadIdx.x) >> 5;
    int lane = threadIdx.x & 31;
    if (w >= N_TOK) return;
    const float* row = x + (size_t)w * DIM;
    float s = 0.f;
    #pragma unroll
    for (int d = lane; d < DIM; d += 32) {
        float v = __ldg(row + d);
        s = __fadd_rn(s, __fmul_rn(v, v));
    }
    #pragma unroll
    for (int o = 16; o > 0; o >>= 1) s = __fadd_rn(s, __shfl_xor_sync(0xffffffffu, s, o));
    if (lane == 0) g_xsq[w] = s;
}

// ---------------- kernel 2: persistent fused fp32-dot + argmin ----------------
// R11 compute skeleton (proven fastest) + double-buffered smem tiles:
// one __syncthreads per stage; stage s+1's LDGs issue before stage s's compute
// and their STS lands after it, hiding the G->S latency inside the compute window.
//   accD[q][p] lanes = (r0*c0, r1*c1), accA[q][p] lanes = (r0*c1, r1*c0)
// Every lane is a serial ascending-d fp32 FMA chain -> bit-identical to R11.
// dist[n][k] = fl( fl(x_sq[n] - 2*dot) + e_sq[k] ), first-index tie-break.
__global__ __launch_bounds__(256, 2) void vq_argmin(const float* __restrict__ x,
                                                    const float* __restrict__ E) {
    extern __shared__ __align__(16) float smem[];
    // buffer b: xs at smem + b*BUF_FLOATS, es at smem + b*BUF_FLOATS + TILE_FLOATS

    const int t  = threadIdx.x;
    const int tx = t & 15;
    const int ty = t >> 4;
    const int lrow  = t >> 1;          // loader row 0..127
    const int lhalf = (t & 1) * 16;    // loader d-offset (16 floats each)

    for (int item = blockIdx.x; item < ITEMS; item += GRID_PERSIST) {
        const int mtile = item >> 5;               // / SPLITS
        const int split = item & (SPLITS - 1);
        const int m0 = mtile * TM;
        const int kbase = split * KS;

        float bestv[8];
        int   besti[8];
        #pragma unroll
        for (int i = 0; i < 8; i++) { bestv[i] = 3.4e38f; besti[i] = 0; }

        const unsigned long long zero2 = pack2(0.f, 0.f);

        const float* xrow = &x[(size_t)(m0 + lrow) * DIM + lhalf];

        for (int c = 0; c < NCHUNK; c++) {
            const int k0 = kbase + c * TN;
            const float* erow = &E[(size_t)(k0 + lrow) * DIM + lhalf];

            unsigned long long accD[4][4], accA[4][4];
            #pragma unroll
            for (int q = 0; q < 4; q++)
                #pragma unroll
                for (int p = 0; p < 4; p++) { accD[q][p] = zero2; accA[q][p] = zero2; }

            // prologue: stage 0 -> buffer 0 (safe: prior readers of buf0 are
            // behind the last stage-sync / item-end sync)
            {
                float4 a0 = *reinterpret_cast<const float4*>(xrow);
                float4 a1 = *reinterpret_cast<const float4*>(xrow + 4);
                float4 a2 = *reinterpret_cast<const float4*>(xrow + 8);
                float4 a3 = *reinterpret_cast<const float4*>(xrow + 12);
                float4 b0 = *reinterpret_cast<const float4*>(erow);
                float4 b1 = *reinterpret_cast<const float4*>(erow + 4);
                float4 b2 = *reinterpret_cast<const float4*>(erow + 8);
                float4 b3 = *reinterpret_cast<const float4*>(erow + 12);
                float* xs0 = smem;
                float* es0 = smem + TILE_FLOATS;
                #define ST16(dst, A, B, C, D2) \
                    (dst)[(lhalf + 0) * TILE_STRIDE + lrow] = (A).x; \
                    (dst)[(lhalf + 1) * TILE_STRIDE + lrow] = (A).y; \
                    (dst)[(lhalf + 2) * TILE_STRIDE + lrow] = (A).z; \
                    (dst)[(lhalf + 3) * TILE_STRIDE + lrow] = (A).w; \
                    (dst)[(lhalf + 4) * TILE_STRIDE + lrow] = (B).x; \
                    (dst)[(lhalf + 5) * TILE_STRIDE + lrow] = (B).y; \
                    (dst)[(lhalf + 6) * TILE_STRIDE + lrow] = (B).z; \
                    (dst)[(lhalf + 7) * TILE_STRIDE + lrow] = (B).w; \
                    (dst)[(lhalf + 8) * TILE_STRIDE + lrow] = (C).x; \
                    (dst)[(lhalf + 9) * TILE_STRIDE + lrow] = (C).y; \
                    (dst)[(lhalf +10) * TILE_STRIDE + lrow] = (C).z; \
                    (dst)[(lhalf +11) * TILE_STRIDE + lrow] = (C).w; \
                    (dst)[(lhalf +12) * TILE_STRIDE + lrow] = (D2).x; \
                    (dst)[(lhalf +13) * TILE_STRIDE + lrow] = (D2).y; \
                    (dst)[(lhalf +14) * TILE_STRIDE + lrow] = (D2).z; \
                    (dst)[(lhalf +15) * TILE_STRIDE + lrow] = (D2).w;
                ST16(xs0, a0, a1, a2, a3)
                ST16(es0, b0, b1, b2, b3)
            }

            for (int s = 0; s < NSTAGE; s++) {
                __syncthreads();   // stage s buffer ready; prev buffer's readers done
                const float* xs = smem + (s & 1) * BUF_FLOATS;
                const float* es = xs + TILE_FLOATS;

                // issue next stage's global loads now; STS after compute
                float4 a0, a1, a2, a3, b0, b1, b2, b3;
                const bool more = (s + 1 < NSTAGE);
                if (more) {
                    const int d1 = (s + 1) * TD;
                    a0 = *reinterpret_cast<const float4*>(xrow + d1);
                    a1 = *reinterpret_cast<const float4*>(xrow + d1 + 4);
                    a2 = *reinterpret_cast<const float4*>(xrow + d1 + 8);
                    a3 = *reinterpret_cast<const float4*>(xrow + d1 + 12);
                    b0 = *reinterpret_cast<const float4*>(erow + d1);
                    b1 = *reinterpret_cast<const float4*>(erow + d1 + 4);
                    b2 = *reinterpret_cast<const float4*>(erow + d1 + 8);
                    b3 = *reinterpret_cast<const float4*>(erow + d1 + 12);
                }

                #pragma unroll 8
                for (int d = 0; d < TD; d++) {
                    unsigned long long xp[4];
                    #pragma unroll
                    for (int q = 0; q < 4; q++)
                        xp[q] = *reinterpret_cast<const unsigned long long*>(
                            &xs[d * TILE_STRIDE + 32 * q + 2 * ty]);
                    #pragma unroll
                    for (int p = 0; p < 4; p++) {
                        float2 e2 = *reinterpret_cast<const float2*>(
                            &es[d * TILE_STRIDE + 32 * p + 2 * tx]);
                        unsigned long long efp = pack2(e2.x, e2.y);
                        unsigned long long erp = pack2(e2.y, e2.x);
                        #pragma unroll
                        for (int q = 0; q < 4; q++) {
                            accD[q][p] = fma2(xp[q], efp, accD[q][p]);
                            accA[q][p] = fma2(xp[q], erp, accA[q][p]);
                        }
                    }
                }

                if (more) {
                    float* xsn = smem + ((s + 1) & 1) * BUF_FLOATS;
                    float* esn = xsn + TILE_FLOATS;
                    ST16(xsn, a0, a1, a2, a3)
                    ST16(esn, b0, b1, b2, b3)
                }
            }
            #undef ST16

            // epilogue: dist = fl( fl(x_sq - 2*dot) + e_sq ); ascending k, strict <
            #pragma unroll
            for (int p = 0; p < 4; p++) {
                int c0 = k0 + 32 * p + 2 * tx;
                float eq0 = __ldg(&g_esq[c0]);
                float eq1 = __ldg(&g_esq[c0 + 1]);
                #pragma unroll
                for (int q = 0; q < 4; q++) {
                    float xq0 = g_xsq[m0 + 32 * q + 2 * ty];
                    float xq1 = g_xsq[m0 + 32 * q + 2 * ty + 1];
                    float d00, d11, a01, a10;
                    unpack2(accD[q][p], d00, d11);   // (r0*c0, r1*c1)
                    unpack2(accA[q][p], a01, a10);   // (r0*c1, r1*c0)
                    float s0 = __fadd_rn(fmaf(-2.f, d00, xq0), eq0);
                    if (s0 < bestv[2 * q]) { bestv[2 * q] = s0; besti[2 * q] = c0; }
                    float s1 = __fadd_rn(fmaf(-2.f, a01, xq0), eq1);
                    if (s1 < bestv[2 * q]) { bestv[2 * q] = s1; besti[2 * q] = c0 + 1; }
                    float s2 = __fadd_rn(fmaf(-2.f, a10, xq1), eq0);
                    if (s2 < bestv[2 * q + 1]) { bestv[2 * q + 1] = s2; besti[2 * q + 1] = c0; }
                    float s3 = __fadd_rn(fmaf(-2.f, d11, xq1), eq1);
                    if (s3 < bestv[2 * q + 1]) { bestv[2 * q + 1] = s3; besti[2 * q + 1] = c0 + 1; }
                }
            }
        }

        // cross-thread reduction per item; alias dead tile buffers
        __syncthreads();
        float* rv = smem;                                   // [TM][16] = 8 KB
        int*   ri = reinterpret_cast<int*>(smem + TM * 16); // [TM][16] = 8 KB
        #pragma unroll
        for (int q = 0; q < 4; q++)
            #pragma unroll
            for (int s2 = 0; s2 < 2; s2++) {
                int row = 32 * q + 2 * ty + s2;
                rv[row * 16 + tx] = bestv[2 * q + s2];
                ri[row * 16 + tx] = besti[2 * q + s2];
            }
        __syncthreads();
        if (t < TM) {
            float bv = rv[t * 16];
            int   bi = ri[t * 16];
            #pragma unroll
            for (int j = 1; j < 16; j++) {
                float v = rv[t * 16 + j];
                int idx = ri[t * 16 + j];
                if (v < bv || (v == bv && idx < bi)) { bv = v; bi = idx; }
            }
            g_pval[split][m0 + t] = bv;
            g_pidx[split][m0 + t] = bi;
        }
        __syncthreads();   // reduction reads done before next item's prologue STS
    }
}

// ---------------- kernel 3: combine splits, gather, write q_st + indices ----------------
__global__ void vq_combine(const float* __restrict__ x, const float* __restrict__ E,
                           float* __restrict__ out) {
    int gw   = (blockIdx.x * blockDim.x + threadIdx.x) >> 5;  // one warp per token row
    int lane = threadIdx.x & 31;
    if (gw >= N_TOK) return;

    float bv = g_pval[0][gw];
    int   bi = g_pidx[0][gw];
    #pragma unroll
    for (int s = 1; s < SPLITS; s++) {
        float v = g_pval[s][gw];
        int idx = g_pidx[s][gw];
        if (v < bv || (v == bv && idx < bi)) { bv = v; bi = idx; }
    }

    const float* er = E + (size_t)bi * DIM;
    const float* xr = x + (size_t)gw * DIM;
    float* qr = out + (size_t)gw * DIM;
    float sq = 0.f;
    #pragma unroll
    for (int d = lane; d < DIM; d += 32) {
        float e  = er[d];
        float xv = xr[d];
        qr[d] = __fadd_rn(xv, __fadd_rn(e, -xv));  // straight-through: fl(x + fl(q - x))
        float df = __fadd_rn(xv, -e);
        sq = __fadd_rn(sq, __fmul_rn(df, df));
    }
    #pragma unroll
    for (int o = 16; o > 0; o >>= 1) sq = __fadd_rn(sq, __shfl_xor_sync(0xffffffffu, sq, o));
    if (lane == 0) {
        g_rowsq[gw] = sq;
        out[(size_t)N_TOK * DIM + gw] = (float)bi;   // indices as float32
    }
}

// ---------------- kernel 4: deterministic loss reduction ----------------
__global__ void vq_loss(float* __restrict__ out) {
    __shared__ float red[256];
    int t = threadIdx.x;
    float s = 0.f;
    for (int i = t; i < N_TOK; i += 256) s += g_rowsq[i];
    red[t] = s;
    __syncthreads();
    #pragma unroll
    for (int o = 128; o > 0; o >>= 1) {
        if (t < o) red[t] += red[t + o];
        __syncthreads();
    }
    if (t == 0) {
        float mse = red[0] / (float)((size_t)N_TOK * DIM);
        size_t base = (size_t)N_TOK * DIM + N_TOK;
        out[base + 0] = 0.25f * mse;   // commitment_loss
        out[base + 1] = mse;           // codebook_loss
        out[base + 2] = 1.25f * mse;   // total_loss
    }
}

// ---------------- entry point ----------------
extern "C" void kernel_launch(void* const* d_in, const int* in_sizes, int n_in,
                              void* d_out, int out_size) {
    (void)in_sizes; (void)n_in; (void)out_size;
    const float* x = (const float*)d_in[0];   // [32*256, 512]
    const float* E = (const float*)d_in[1];   // [8192, 512]
    float* out = (float*)d_out;

    // Opt into >48KB dynamic smem (attribute set, not an allocation; idempotent,
    // executes immediately — not a captured stream op).
    cudaFuncSetAttribute(vq_argmin, cudaFuncAttributeMaxDynamicSharedMemorySize, SMEM_BYTES);

    vq_esq<<<K_CODES * 32 / 256, 256>>>(E);
    vq_xsq<<<N_TOK * 32 / 256, 256>>>(x);
    vq_argmin<<<GRID_PERSIST, 256, SMEM_BYTES>>>(x, E);
    vq_combine<<<N_TOK * 32 / 256, 256>>>(x, E, out);
    vq_loss<<<1, 256>>>(out);
}